// round 1
// baseline (speedup 1.0000x reference)
#include <cuda_runtime.h>

// Problem constants (from reference_code)
#define Hn    50000
#define INn   50000
#define NNZn  800000
#define Bn    8
#define Tn    32

// ---------------- device scratch (static globals; no runtime allocation) ----
__device__ float g_xT[(size_t)Tn * INn * Bn];      // x transposed to (T, IN, B)  51.2 MB
__device__ float g_ihpre[(size_t)Tn * Hn * Bn];    // ih spmm + bias, (T, H, B)   51.2 MB
__device__ float g_h[2][Hn * Bn];                  // ping-pong hidden state (H, B)
__device__ int   g_rowptr_hh[Hn + 1];
__device__ int   g_rowptr_ih[Hn + 1];
__device__ int   g_cnt_hh[Hn];
__device__ int   g_cnt_ih[Hn];
__device__ int   g_cur_hh[Hn];
__device__ int   g_cur_ih[Hn];
__device__ int2  g_pairs_hh[NNZn];                 // {col, float_as_int(val)}
__device__ int2  g_pairs_ih[NNZn];

// ---------------- preprocessing -------------------------------------------

// zero h0 and the histogram counters
__global__ void init_kernel() {
    int i = blockIdx.x * blockDim.x + threadIdx.x;
    if (i < Hn * Bn) g_h[0][i] = 0.0f;
    if (i < Hn) { g_cnt_hh[i] = 0; g_cnt_ih[i] = 0; }
}

__global__ void hist_kernel(const int* __restrict__ rows, int* __restrict__ cnt) {
    int j = blockIdx.x * blockDim.x + threadIdx.x;
    if (j < NNZn) atomicAdd(&cnt[rows[j]], 1);
}

// single-block exclusive scan over Hn counters -> rowptr and cursor
__global__ void scan_kernel(const int* __restrict__ cnt,
                            int* __restrict__ rowptr,
                            int* __restrict__ cursor) {
    __shared__ int part[1024];
    const int chunk = (Hn + 1023) / 1024;
    int t = threadIdx.x;
    int beg = t * chunk;
    int end = min(Hn, beg + chunk);
    int s = 0;
    for (int i = beg; i < end; ++i) s += cnt[i];
    part[t] = s;
    __syncthreads();
    if (t == 0) {
        int run = 0;
        for (int i = 0; i < 1024; ++i) { int v = part[i]; part[i] = run; run += v; }
        rowptr[Hn] = run;
    }
    __syncthreads();
    int run = part[t];
    for (int i = beg; i < end; ++i) {
        rowptr[i] = run;
        cursor[i] = run;
        run += cnt[i];
    }
}

__global__ void scatter_kernel(const int* __restrict__ rows,
                               const int* __restrict__ cols,
                               const float* __restrict__ vals,
                               int* __restrict__ cursor,
                               int2* __restrict__ pairs) {
    int j = blockIdx.x * blockDim.x + threadIdx.x;
    if (j >= NNZn) return;
    int r = rows[j];
    int p = atomicAdd(&cursor[r], 1);
    pairs[p] = make_int2(cols[j], __float_as_int(vals[j]));
}

// x (B, T, IN) -> g_xT (T, IN, B)
__global__ void transpose_kernel(const float* __restrict__ x) {
    int idx = blockIdx.x * blockDim.x + threadIdx.x;   // over T*IN
    if (idx >= Tn * INn) return;
    int t = idx / INn;
    int c = idx - t * INn;
    float v[Bn];
#pragma unroll
    for (int b = 0; b < Bn; ++b)
        v[b] = x[(size_t)b * Tn * INn + (size_t)t * INn + c];
    float4* dst = reinterpret_cast<float4*>(&g_xT[(size_t)idx * Bn]);
    dst[0] = make_float4(v[0], v[1], v[2], v[3]);
    dst[1] = make_float4(v[4], v[5], v[6], v[7]);
}

// ---------------- main compute ---------------------------------------------

// ih_pre[t, r, b] = bias[r] + sum_j ih_val[j] * xT[t, col[j], b]
// 8 threads per (t, row) task, thread = batch lane
__global__ void ih_kernel(const float* __restrict__ bias) {
    int g = blockIdx.x * 32 + (threadIdx.x >> 3);
    if (g >= Tn * Hn) return;
    int b = threadIdx.x & 7;
    int t = g / Hn;
    int r = g - t * Hn;
    float acc = bias[r];
    int jb = g_rowptr_ih[r];
    int je = g_rowptr_ih[r + 1];
    const float* xt = g_xT + (size_t)t * INn * Bn;
    for (int j = jb; j < je; ++j) {
        int2 p = g_pairs_ih[j];
        acc += __int_as_float(p.y) * xt[p.x * Bn + b];
    }
    g_ihpre[(size_t)g * Bn + b] = acc;
}

// one recurrence step: h_next = tanh(hh @ h_prev + ih_pre[t]); also writes output
__global__ void step_kernel(const float* __restrict__ hprev,
                            float* __restrict__ hnext,
                            const float* __restrict__ ihpre_t,
                            float* __restrict__ out_t) {  // d_out + t*H
    int g = blockIdx.x * 32 + (threadIdx.x >> 3);
    if (g >= Hn) return;
    int b = threadIdx.x & 7;
    float acc = ihpre_t[g * Bn + b];
    int jb = g_rowptr_hh[g];
    int je = g_rowptr_hh[g + 1];
    for (int j = jb; j < je; ++j) {
        int2 p = g_pairs_hh[j];
        acc += __int_as_float(p.y) * hprev[p.x * Bn + b];
    }
    float hv = tanhf(acc);
    hnext[g * Bn + b] = hv;
    out_t[(size_t)b * Tn * Hn + g] = hv;   // output layout (B, T, H)
}

// ---------------- launch ----------------------------------------------------

extern "C" void kernel_launch(void* const* d_in, const int* in_sizes, int n_in,
                              void* d_out, int out_size) {
    const float* x        = (const float*)d_in[0];   // (B, T, IN)
    const float* hh_vals  = (const float*)d_in[1];   // (NNZ,)
    const float* hh_bias  = (const float*)d_in[2];   // (H, 1)
    const float* ih_vals  = (const float*)d_in[3];   // (NNZ,)
    const int*   hh_idx   = (const int*)d_in[4];     // (2, NNZ): rows then cols
    const int*   ih_idx   = (const int*)d_in[5];     // (2, NNZ)
    float*       out      = (float*)d_out;           // (B, T, H)

    // resolve scratch symbol addresses (host-side, capture-safe)
    float *ihpre_p, *h_p;  int *cnt_hh_p, *cnt_ih_p, *rp_hh_p, *rp_ih_p, *cur_hh_p, *cur_ih_p;
    int2 *pr_hh_p, *pr_ih_p;
    cudaGetSymbolAddress((void**)&ihpre_p,  g_ihpre);
    cudaGetSymbolAddress((void**)&h_p,      g_h);
    cudaGetSymbolAddress((void**)&cnt_hh_p, g_cnt_hh);
    cudaGetSymbolAddress((void**)&cnt_ih_p, g_cnt_ih);
    cudaGetSymbolAddress((void**)&rp_hh_p,  g_rowptr_hh);
    cudaGetSymbolAddress((void**)&rp_ih_p,  g_rowptr_ih);
    cudaGetSymbolAddress((void**)&cur_hh_p, g_cur_hh);
    cudaGetSymbolAddress((void**)&cur_ih_p, g_cur_ih);
    cudaGetSymbolAddress((void**)&pr_hh_p,  g_pairs_hh);
    cudaGetSymbolAddress((void**)&pr_ih_p,  g_pairs_ih);

    const int TPB = 256;

    // 1) init counters + h0
    init_kernel<<<(Hn * Bn + TPB - 1) / TPB, TPB>>>();

    // 2) histograms (rows are the first NNZ entries of each index tensor)
    hist_kernel<<<(NNZn + TPB - 1) / TPB, TPB>>>(hh_idx, cnt_hh_p);
    hist_kernel<<<(NNZn + TPB - 1) / TPB, TPB>>>(ih_idx, cnt_ih_p);

    // 3) scans -> rowptr + cursor
    scan_kernel<<<1, 1024>>>(cnt_hh_p, rp_hh_p, cur_hh_p);
    scan_kernel<<<1, 1024>>>(cnt_ih_p, rp_ih_p, cur_ih_p);

    // 4) scatter into CSR pair arrays
    scatter_kernel<<<(NNZn + TPB - 1) / TPB, TPB>>>(hh_idx, hh_idx + NNZn, hh_vals,
                                                    cur_hh_p, pr_hh_p);
    scatter_kernel<<<(NNZn + TPB - 1) / TPB, TPB>>>(ih_idx, ih_idx + NNZn, ih_vals,
                                                    cur_ih_p, pr_ih_p);

    // 5) transpose x -> (T, IN, B)
    transpose_kernel<<<(Tn * INn + TPB - 1) / TPB, TPB>>>(x);

    // 6) all 32 input-path spmms in parallel (+ bias folded in)
    ih_kernel<<<(Tn * Hn + 31) / 32, TPB>>>(hh_bias);

    // 7) sequential recurrence: 32 fused spmm+tanh steps
    const int step_grid = (Hn + 31) / 32;
    for (int t = 0; t < Tn; ++t) {
        const float* hprev = h_p + (size_t)(t & 1) * Hn * Bn;
        float*       hnext = h_p + (size_t)((t + 1) & 1) * Hn * Bn;
        step_kernel<<<step_grid, TPB>>>(hprev, hnext,
                                        ihpre_p + (size_t)t * Hn * Bn,
                                        out + (size_t)t * Hn);
    }
}

// round 2
// speedup vs baseline: 1.3968x; 1.3968x over previous
#include <cuda_runtime.h>

// Problem constants (from reference_code)
#define Hn    50000
#define INn   50000
#define NNZn  800000
#define Bn    8
#define Tn    32

#define NB    ((Hn + 255) / 256)   // 196 scan blocks per matrix

// ---------------- device scratch (static globals; no runtime allocation) ----
__device__ float g_xT[(size_t)Tn * INn * Bn];      // x transposed -> (T, IN, B)
__device__ float g_ihpre[(size_t)Tn * Hn * Bn];    // ih spmm + bias, (T, H, B)
__device__ float g_h[2][Hn * Bn];                  // ping-pong hidden state (H, B)
__device__ int   g_rowptr[2][Hn + 1];              // [0]=hh, [1]=ih
__device__ int   g_cnt[2][Hn];
__device__ int   g_cur[2][Hn];
__device__ int   g_bsum[2][256];
__device__ int2  g_pairs[2][NNZn];                 // {col, float_as_int(val)}

// ---------------- preprocessing -------------------------------------------

// zero h0 and the histogram counters
__global__ void init_kernel() {
    int i = blockIdx.x * blockDim.x + threadIdx.x;
    if (i < Hn * Bn) g_h[0][i] = 0.0f;
    if (i < Hn) { g_cnt[0][i] = 0; g_cnt[1][i] = 0; }
}

// fused histogram over both matrices (gridDim.y selects matrix)
__global__ void hist_kernel(const int* __restrict__ hh_idx,
                            const int* __restrict__ ih_idx) {
    int j = blockIdx.x * blockDim.x + threadIdx.x;
    int m = blockIdx.y;
    if (j >= NNZn) return;
    const int* rows = m ? ih_idx : hh_idx;
    atomicAdd(&g_cnt[m][rows[j]], 1);
}

// phase 1: per-block inclusive scan of 256 counts; write local-exclusive +
// block total
__global__ void scan1_kernel() {
    int m = blockIdx.y;
    int i = blockIdx.x * 256 + threadIdx.x;
    int v = (i < Hn) ? g_cnt[m][i] : 0;
    int lane = threadIdx.x & 31, w = threadIdx.x >> 5;
    int x = v;
#pragma unroll
    for (int o = 1; o < 32; o <<= 1) {
        int y = __shfl_up_sync(~0u, x, o);
        if (lane >= o) x += y;
    }
    __shared__ int wsum[8];
    if (lane == 31) wsum[w] = x;
    __syncthreads();
    if (w == 0 && lane < 8) {
        int y = wsum[lane];
#pragma unroll
        for (int o = 1; o < 8; o <<= 1) {
            int z = __shfl_up_sync(0xffu, y, o);
            if (lane >= o) y += z;
        }
        wsum[lane] = y;
    }
    __syncthreads();
    int incl = x + (w > 0 ? wsum[w - 1] : 0);
    if (i < Hn) g_rowptr[m][i] = incl - v;          // local exclusive
    if (threadIdx.x == 255) g_bsum[m][blockIdx.x] = incl;
}

// phase 2: scan the (<=256) block sums; one block per matrix
__global__ void scan2_kernel() {
    int m = blockIdx.y;
    int t = threadIdx.x;
    int v = (t < NB) ? g_bsum[m][t] : 0;
    int lane = t & 31, w = t >> 5;
    int x = v;
#pragma unroll
    for (int o = 1; o < 32; o <<= 1) {
        int y = __shfl_up_sync(~0u, x, o);
        if (lane >= o) x += y;
    }
    __shared__ int wsum[8];
    if (lane == 31) wsum[w] = x;
    __syncthreads();
    if (w == 0 && lane < 8) {
        int y = wsum[lane];
#pragma unroll
        for (int o = 1; o < 8; o <<= 1) {
            int z = __shfl_up_sync(0xffu, y, o);
            if (lane >= o) y += z;
        }
        wsum[lane] = y;
    }
    __syncthreads();
    int incl = x + (w > 0 ? wsum[w - 1] : 0);
    if (t < NB) g_bsum[m][t] = incl - v;            // exclusive block offset
    if (t == 255) g_rowptr[m][Hn] = incl;           // total nnz
}

// phase 3: add block offsets; materialize rowptr + scatter cursor
__global__ void scan3_kernel() {
    int m = blockIdx.y;
    int i = blockIdx.x * 256 + threadIdx.x;
    if (i >= Hn) return;
    int r = g_rowptr[m][i] + g_bsum[m][blockIdx.x];
    g_rowptr[m][i] = r;
    g_cur[m][i]    = r;
}

// fused scatter into CSR pair arrays (gridDim.y selects matrix)
__global__ void scatter_kernel(const int* __restrict__ hh_idx,
                               const float* __restrict__ hh_vals,
                               const int* __restrict__ ih_idx,
                               const float* __restrict__ ih_vals) {
    int j = blockIdx.x * blockDim.x + threadIdx.x;
    int m = blockIdx.y;
    if (j >= NNZn) return;
    const int*   idx  = m ? ih_idx  : hh_idx;
    const float* vals = m ? ih_vals : hh_vals;
    int r = idx[j];
    int c = idx[NNZn + j];
    int p = atomicAdd(&g_cur[m][r], 1);
    g_pairs[m][p] = make_int2(c, __float_as_int(vals[j]));
}

// x (B, T, IN) -> g_xT (T, IN, B)
__global__ void transpose_kernel(const float* __restrict__ x) {
    int idx = blockIdx.x * blockDim.x + threadIdx.x;   // over T*IN
    if (idx >= Tn * INn) return;
    int t = idx / INn;
    int c = idx - t * INn;
    float v[Bn];
#pragma unroll
    for (int b = 0; b < Bn; ++b)
        v[b] = x[(size_t)b * Tn * INn + (size_t)t * INn + c];
    float4* dst = reinterpret_cast<float4*>(&g_xT[(size_t)idx * Bn]);
    dst[0] = make_float4(v[0], v[1], v[2], v[3]);
    dst[1] = make_float4(v[4], v[5], v[6], v[7]);
}

// ---------------- main compute ---------------------------------------------

// ih_pre[t, r, b] = bias[r] + sum_j ih_val[j] * xT[t, col[j], b]
// 8 threads per row task (thread = batch lane); all 32 timesteps accumulated
// in registers so each CSR pair is read exactly once.
__global__ void ih_kernel(const float* __restrict__ bias) {
    int g = blockIdx.x * 32 + (threadIdx.x >> 3);      // row
    if (g >= Hn) return;
    int b = threadIdx.x & 7;
    float bv = bias[g];
    float acc[Tn];
#pragma unroll
    for (int t = 0; t < Tn; ++t) acc[t] = bv;
    int jb = g_rowptr[1][g];
    int je = g_rowptr[1][g + 1];
    for (int j = jb; j < je; ++j) {
        int2 p = g_pairs[1][j];
        float v = __int_as_float(p.y);
        const float* xp = g_xT + (size_t)p.x * Bn + b;
#pragma unroll
        for (int t = 0; t < Tn; ++t)
            acc[t] += v * xp[(size_t)t * INn * Bn];
    }
#pragma unroll
    for (int t = 0; t < Tn; ++t)
        g_ihpre[((size_t)t * Hn + g) * Bn + b] = acc[t];
}

// one recurrence step: h_next = tanh(hh @ h_prev + ih_pre[t]); writes output
__global__ void step_kernel(const float* __restrict__ hprev,
                            float* __restrict__ hnext,
                            const float* __restrict__ ihpre_t,
                            float* __restrict__ out_t) {  // d_out + t*H
    int g = blockIdx.x * 32 + (threadIdx.x >> 3);
    if (g >= Hn) return;
    int b = threadIdx.x & 7;
    float acc = ihpre_t[g * Bn + b];
    int jb = g_rowptr[0][g];
    int je = g_rowptr[0][g + 1];
    for (int j = jb; j < je; ++j) {
        int2 p = g_pairs[0][j];
        acc += __int_as_float(p.y) * hprev[p.x * Bn + b];
    }
    float hv = tanhf(acc);
    hnext[g * Bn + b] = hv;
    out_t[(size_t)b * Tn * Hn + g] = hv;   // output layout (B, T, H)
}

// ---------------- launch ----------------------------------------------------

extern "C" void kernel_launch(void* const* d_in, const int* in_sizes, int n_in,
                              void* d_out, int out_size) {
    const float* x        = (const float*)d_in[0];   // (B, T, IN)
    const float* hh_vals  = (const float*)d_in[1];   // (NNZ,)
    const float* hh_bias  = (const float*)d_in[2];   // (H, 1)
    const float* ih_vals  = (const float*)d_in[3];   // (NNZ,)
    const int*   hh_idx   = (const int*)d_in[4];     // (2, NNZ): rows then cols
    const int*   ih_idx   = (const int*)d_in[5];     // (2, NNZ)
    float*       out      = (float*)d_out;           // (B, T, H)

    float *ihpre_p, *h_p;
    cudaGetSymbolAddress((void**)&ihpre_p, g_ihpre);
    cudaGetSymbolAddress((void**)&h_p,     g_h);

    const int TPB = 256;

    // 1) init counters + h0
    init_kernel<<<(Hn * Bn + TPB - 1) / TPB, TPB>>>();

    // 2) fused histograms
    dim3 hg((NNZn + TPB - 1) / TPB, 2);
    hist_kernel<<<hg, TPB>>>(hh_idx, ih_idx);

    // 3) hierarchical scans -> rowptr + cursor (both matrices at once)
    dim3 sg(NB, 2);
    scan1_kernel<<<sg, 256>>>();
    scan2_kernel<<<dim3(1, 2), 256>>>();
    scan3_kernel<<<sg, 256>>>();

    // 4) fused scatter into CSR pair arrays
    scatter_kernel<<<hg, TPB>>>(hh_idx, hh_vals, ih_idx, ih_vals);

    // 5) transpose x -> (T, IN, B)
    transpose_kernel<<<(Tn * INn + TPB - 1) / TPB, TPB>>>(x);

    // 6) all 32 input-path spmms in parallel (+ bias folded in)
    ih_kernel<<<(Hn + 31) / 32, TPB>>>(hh_bias);

    // 7) sequential recurrence: 32 fused spmm+tanh steps
    const int step_grid = (Hn + 31) / 32;
    for (int t = 0; t < Tn; ++t) {
        const float* hprev = h_p + (size_t)(t & 1) * Hn * Bn;
        float*       hnext = h_p + (size_t)((t + 1) & 1) * Hn * Bn;
        step_kernel<<<step_grid, TPB>>>(hprev, hnext,
                                        ihpre_p + (size_t)t * Hn * Bn,
                                        out + (size_t)t * Hn);
    }
}